// round 13
// baseline (speedup 1.0000x reference)
#include <cuda_runtime.h>
#include <cuda_bf16.h>
#include <mma.h>
#include <cstdint>

using namespace nvcuda;

// GCNAggregator 2-kernel pipeline:
//   K1: mean[row] = mean_s features[sample[row][s]] -> d_out (fp32)
//       idx distributed via shfl (1 LDG per row instead of 25)
//   K2: persistent bf16-split WMMA GEMM + relu, 512-thr CTAs (32 warps/SM).

#define D_DIM 128
#define S_SAMPLES 25
#define N_NODES 100000

// ---------------- K1: gather + mean ----------------
#define K1_THREADS 256
#define K1_WARPS 8
#define K1_GRID 1024          // 1024*8 warps * 4 rows = 32768 rows

__global__ __launch_bounds__(K1_THREADS)
void gather_mean_kernel(const float* __restrict__ features,
                        const int* __restrict__ sample,
                        float* __restrict__ mean_out)
{
    const int wid  = threadIdx.x >> 5;
    const int lane = threadIdx.x & 31;
    const int k0   = lane * 4;
    const int wglobal = blockIdx.x * K1_WARPS + wid;   // 0..8191

    #pragma unroll
    for (int r = 0; r < 4; r++) {
        const int row = wglobal + r * (K1_GRID * K1_WARPS);
        const int* idxp = sample + (long long)row * S_SAMPLES;

        // one coalesced LDG for all 25 indices (lanes 25-31 predicated off)
        int idxv = 0;
        if (lane < S_SAMPLES) idxv = __ldg(&idxp[lane]);

        float4 acc = make_float4(0.f, 0.f, 0.f, 0.f);
        #pragma unroll
        for (int s = 0; s < S_SAMPLES; s++) {
            int node = __shfl_sync(0xffffffffu, idxv, s);   // ALU, not L1
            node = min(max(node, 0), N_NODES - 1);          // defensive clamp
            const float4 v = *reinterpret_cast<const float4*>(
                &features[(long long)node * D_DIM + k0]);
            acc.x += v.x; acc.y += v.y; acc.z += v.z; acc.w += v.w;
        }
        const float inv = 1.0f / (float)S_SAMPLES;
        acc.x *= inv; acc.y *= inv; acc.z *= inv; acc.w *= inv;
        *reinterpret_cast<float4*>(&mean_out[(long long)row * D_DIM + k0]) = acc;
    }
}

// ---------------- K2: persistent WMMA GEMM + relu, 512 threads ----------------
#define K2_THREADS 512
#define K2_GRID 256
#define TILE_ROWS 64
#define TILES_PER_CTA 2          // 256 * 2 * 64 = 32768 rows
#define LDS_A 136                // bf16 stride, 272B rows
#define SA_ELEMS (TILE_ROWS * LDS_A)   // 8704
#define SW_ELEMS (D_DIM * LDS_A)       // 17408

__global__ __launch_bounds__(K2_THREADS, 2)
void gemm_relu_kernel(const float* __restrict__ W,
                      float* __restrict__ inout)   // means in, relu out
{
    extern __shared__ __nv_bfloat16 smem[];
    __nv_bfloat16* sAhi = smem;                    // [64][136]
    __nv_bfloat16* sAlo = sAhi + SA_ELEMS;
    __nv_bfloat16* sWhi = sAlo + SA_ELEMS;         // [128][136]
    __nv_bfloat16* sWlo = sWhi + SW_ELEMS;

    const int tid  = threadIdx.x;
    const int wid  = tid >> 5;                     // 0..15
    const long long ctaRow0 = (long long)blockIdx.x * (TILES_PER_CTA * TILE_ROWS);

    // ---- Stage W once: fp32 -> bf16 hi/lo (512 thr x 8 float4) ----
    #pragma unroll
    for (int i = 0; i < 8; i++) {
        const int idx = tid + i * K2_THREADS;     // 0..4095 float4
        const int k   = idx >> 5;
        const int n0  = (idx & 31) * 4;
        const float4 v = *reinterpret_cast<const float4*>(&W[k * D_DIM + n0]);
        const __nv_bfloat16 hx = __float2bfloat16(v.x);
        const __nv_bfloat16 hy = __float2bfloat16(v.y);
        const __nv_bfloat16 hz = __float2bfloat16(v.z);
        const __nv_bfloat16 hw = __float2bfloat16(v.w);
        *reinterpret_cast<__nv_bfloat162*>(&sWhi[k * LDS_A + n0]) =
            __nv_bfloat162(hx, hy);
        *reinterpret_cast<__nv_bfloat162*>(&sWhi[k * LDS_A + n0 + 2]) =
            __nv_bfloat162(hz, hw);
        *reinterpret_cast<__nv_bfloat162*>(&sWlo[k * LDS_A + n0]) =
            __nv_bfloat162(__float2bfloat16(v.x - __bfloat162float(hx)),
                           __float2bfloat16(v.y - __bfloat162float(hy)));
        *reinterpret_cast<__nv_bfloat162*>(&sWlo[k * LDS_A + n0 + 2]) =
            __nv_bfloat162(__float2bfloat16(v.z - __bfloat162float(hz)),
                           __float2bfloat16(v.w - __bfloat162float(hw)));
    }

    // Per-thread A-prefetch: 64 rows x 32 float4 = 2048 / 512 thr = 4 float4.
    float4 pf[4];
    #pragma unroll
    for (int i = 0; i < 4; i++) {
        const int idx = tid + i * K2_THREADS;
        pf[i] = *reinterpret_cast<const float4*>(
            &inout[(ctaRow0 + (idx >> 5)) * D_DIM + (idx & 31) * 4]);
    }

    const int wr = (wid >> 2) * 16;   // 0,16,32,48
    const int wc = (wid & 3) * 32;    // 0,32,64,96

    for (int t = 0; t < TILES_PER_CTA; t++) {
        const long long tileRow0 = ctaRow0 + (long long)t * TILE_ROWS;

        // ---- STS current tile (fp32 -> bf16 hi/lo) ----
        #pragma unroll
        for (int i = 0; i < 4; i++) {
            const int idx = tid + i * K2_THREADS;
            const int r   = idx >> 5;
            const int c0  = (idx & 31) * 4;
            const float4 v = pf[i];
            const __nv_bfloat16 hx = __float2bfloat16(v.x);
            const __nv_bfloat16 hy = __float2bfloat16(v.y);
            const __nv_bfloat16 hz = __float2bfloat16(v.z);
            const __nv_bfloat16 hw = __float2bfloat16(v.w);
            *reinterpret_cast<__nv_bfloat162*>(&sAhi[r * LDS_A + c0]) =
                __nv_bfloat162(hx, hy);
            *reinterpret_cast<__nv_bfloat162*>(&sAhi[r * LDS_A + c0 + 2]) =
                __nv_bfloat162(hz, hw);
            *reinterpret_cast<__nv_bfloat162*>(&sAlo[r * LDS_A + c0]) =
                __nv_bfloat162(__float2bfloat16(v.x - __bfloat162float(hx)),
                               __float2bfloat16(v.y - __bfloat162float(hy)));
            *reinterpret_cast<__nv_bfloat162*>(&sAlo[r * LDS_A + c0 + 2]) =
                __nv_bfloat162(__float2bfloat16(v.z - __bfloat162float(hz)),
                               __float2bfloat16(v.w - __bfloat162float(hw)));
        }
        __syncthreads();

        // ---- Prefetch next tile ----
        if (t + 1 < TILES_PER_CTA) {
            const long long nRow0 = tileRow0 + TILE_ROWS;
            #pragma unroll
            for (int i = 0; i < 4; i++) {
                const int idx = tid + i * K2_THREADS;
                pf[i] = *reinterpret_cast<const float4*>(
                    &inout[(nRow0 + (idx >> 5)) * D_DIM + (idx & 31) * 4]);
            }
        }

        // ---- WMMA: warp tile 16 rows x 32 cols, 3-term bf16 split ----
        wmma::fragment<wmma::accumulator, 16, 16, 16, float> acc[2];
        wmma::fill_fragment(acc[0], 0.0f);
        wmma::fill_fragment(acc[1], 0.0f);

        #pragma unroll
        for (int ks = 0; ks < D_DIM / 16; ks++) {
            wmma::fragment<wmma::matrix_a, 16, 16, 16, __nv_bfloat16,
                           wmma::row_major> aHi, aLo;
            wmma::fragment<wmma::matrix_b, 16, 16, 16, __nv_bfloat16,
                           wmma::row_major> bHi[2], bLo[2];

            const __nv_bfloat16* pa = &sAhi[wr * LDS_A + ks * 16];
            wmma::load_matrix_sync(aHi, pa, LDS_A);
            wmma::load_matrix_sync(aLo, pa + SA_ELEMS, LDS_A);     // sAlo

            #pragma unroll
            for (int j = 0; j < 2; j++) {
                const __nv_bfloat16* pb =
                    &sWhi[(ks * 16) * LDS_A + wc + j * 16];
                wmma::load_matrix_sync(bHi[j], pb, LDS_A);
                wmma::load_matrix_sync(bLo[j], pb + SW_ELEMS, LDS_A); // sWlo
            }

            #pragma unroll
            for (int j = 0; j < 2; j++) {
                wmma::mma_sync(acc[j], aHi, bHi[j], acc[j]);
                wmma::mma_sync(acc[j], aHi, bLo[j], acc[j]);
                wmma::mma_sync(acc[j], aLo, bHi[j], acc[j]);
            }
        }

        // ---- Epilogue: relu + store ----
        #pragma unroll
        for (int j = 0; j < 2; j++) {
            #pragma unroll
            for (int e = 0; e < acc[j].num_elements; e++)
                acc[j].x[e] = fmaxf(acc[j].x[e], 0.0f);
            wmma::store_matrix_sync(
                &inout[(tileRow0 + wr) * D_DIM + wc + j * 16],
                acc[j], D_DIM, wmma::mem_row_major);
        }
        __syncthreads();   // protect sA before next STS
    }
}

extern "C" void kernel_launch(void* const* d_in, const int* in_sizes, int n_in,
                              void* d_out, int out_size)
{
    // Identify inputs by element count — robust to d_in ordering.
    int imax = 0, imin = 0;
    for (int i = 1; i < 3 && i < n_in; i++) {
        if (in_sizes[i] > in_sizes[imax]) imax = i;
        if (in_sizes[i] < in_sizes[imin]) imin = i;
    }
    const int imid = 3 - imax - imin;

    const float* features = (const float*)d_in[imax];
    const float* W        = (const float*)d_in[imin];
    const int*   sample   = (const int*)d_in[imid];

    float* out = (float*)d_out;

    const int smem_bytes = (2 * SA_ELEMS + 2 * SW_ELEMS) * sizeof(__nv_bfloat16);
    // = (2*8704 + 2*17408) * 2 = 104,448 B  (2 CTAs/SM: 208.9 KB < 227 KB)

    cudaFuncSetAttribute(gemm_relu_kernel,
                         cudaFuncAttributeMaxDynamicSharedMemorySize,
                         smem_bytes);

    gather_mean_kernel<<<K1_GRID, K1_THREADS>>>(features, sample, out);
    gemm_relu_kernel<<<K2_GRID, K2_THREADS, smem_bytes>>>(W, out);
}

// round 14
// speedup vs baseline: 1.2087x; 1.2087x over previous
#include <cuda_runtime.h>
#include <cuda_bf16.h>
#include <mma.h>
#include <cstdint>

using namespace nvcuda;

// GCNAggregator 2-kernel pipeline:
//   K1: mean[row] = mean_s features[sample[row][s]] -> d_out (fp32)
//   K2: bf16-split WMMA GEMM + relu, fragments double-buffered across ks.

#define D_DIM 128
#define S_SAMPLES 25
#define N_NODES 100000

// ---------------- K1: gather + mean (R12 proven form) ----------------
#define K1_THREADS 256
#define K1_WARPS 8
#define K1_GRID 1024          // 1024*8 warps * 4 rows = 32768 rows

__global__ __launch_bounds__(K1_THREADS)
void gather_mean_kernel(const float* __restrict__ features,
                        const int* __restrict__ sample,
                        float* __restrict__ mean_out)
{
    const int wid  = threadIdx.x >> 5;
    const int lane = threadIdx.x & 31;
    const int k0   = lane * 4;
    const int wglobal = blockIdx.x * K1_WARPS + wid;   // 0..8191

    #pragma unroll
    for (int r = 0; r < 4; r++) {
        const int row = wglobal + r * (K1_GRID * K1_WARPS);
        const int* idxp = sample + (long long)row * S_SAMPLES;

        float4 acc = make_float4(0.f, 0.f, 0.f, 0.f);
        #pragma unroll
        for (int s = 0; s < S_SAMPLES; s++) {
            int node = __ldg(&idxp[s]);                 // uniform broadcast
            node = min(max(node, 0), N_NODES - 1);      // defensive clamp
            const float4 v = *reinterpret_cast<const float4*>(
                &features[(long long)node * D_DIM + k0]);
            acc.x += v.x; acc.y += v.y; acc.z += v.z; acc.w += v.w;
        }
        const float inv = 1.0f / (float)S_SAMPLES;
        acc.x *= inv; acc.y *= inv; acc.z *= inv; acc.w *= inv;
        *reinterpret_cast<float4*>(&mean_out[(long long)row * D_DIM + k0]) = acc;
    }
}

// ---------------- K2: WMMA GEMM + relu, ks-pipelined fragments ----------------
#define K2_THREADS 256
#define K2_ROWS 64
#define LDS_A 136                      // bf16 stride, 272B rows, conflict-free
#define SA_ELEMS (K2_ROWS * LDS_A)     // 8704
#define SW_ELEMS (D_DIM * LDS_A)       // 17408

struct FragSet {
    wmma::fragment<wmma::matrix_a, 16, 16, 16, __nv_bfloat16,
                   wmma::row_major> aHi[2], aLo[2];
    wmma::fragment<wmma::matrix_b, 16, 16, 16, __nv_bfloat16,
                   wmma::row_major> bHi[2], bLo[2];
};

__device__ __forceinline__ void load_frags(
    FragSet& f, const __nv_bfloat16* sAhi, const __nv_bfloat16* sWhi,
    int wr, int wc, int ks)
{
    #pragma unroll
    for (int i = 0; i < 2; i++) {
        const __nv_bfloat16* pa = &sAhi[(wr + i * 16) * LDS_A + ks * 16];
        wmma::load_matrix_sync(f.aHi[i], pa, LDS_A);
        wmma::load_matrix_sync(f.aLo[i], pa + SA_ELEMS, LDS_A);    // sAlo
    }
    #pragma unroll
    for (int j = 0; j < 2; j++) {
        const __nv_bfloat16* pb = &sWhi[(ks * 16) * LDS_A + wc + j * 16];
        wmma::load_matrix_sync(f.bHi[j], pb, LDS_A);
        wmma::load_matrix_sync(f.bLo[j], pb + SW_ELEMS, LDS_A);    // sWlo
    }
}

__global__ __launch_bounds__(K2_THREADS, 2)
void gemm_relu_kernel(const float* __restrict__ W,
                      float* __restrict__ inout)   // means in, relu out
{
    extern __shared__ __nv_bfloat16 smem[];
    __nv_bfloat16* sAhi = smem;                    // [64][136]
    __nv_bfloat16* sAlo = sAhi + SA_ELEMS;
    __nv_bfloat16* sWhi = sAlo + SA_ELEMS;         // [128][136]
    __nv_bfloat16* sWlo = sWhi + SW_ELEMS;

    const int tid  = threadIdx.x;
    const int wid  = tid >> 5;
    const int row0 = blockIdx.x * K2_ROWS;

    // ---- Stage W: fp32 -> bf16 hi/lo ----
    #pragma unroll
    for (int i = 0; i < 16; i++) {
        const int idx = tid + i * K2_THREADS;     // 0..4095 float4
        const int k   = idx >> 5;
        const int n0  = (idx & 31) * 4;
        const float4 v = *reinterpret_cast<const float4*>(&W[k * D_DIM + n0]);
        const __nv_bfloat16 hx = __float2bfloat16(v.x);
        const __nv_bfloat16 hy = __float2bfloat16(v.y);
        const __nv_bfloat16 hz = __float2bfloat16(v.z);
        const __nv_bfloat16 hw = __float2bfloat16(v.w);
        *reinterpret_cast<__nv_bfloat162*>(&sWhi[k * LDS_A + n0]) =
            __nv_bfloat162(hx, hy);
        *reinterpret_cast<__nv_bfloat162*>(&sWhi[k * LDS_A + n0 + 2]) =
            __nv_bfloat162(hz, hw);
        *reinterpret_cast<__nv_bfloat162*>(&sWlo[k * LDS_A + n0]) =
            __nv_bfloat162(__float2bfloat16(v.x - __bfloat162float(hx)),
                           __float2bfloat16(v.y - __bfloat162float(hy)));
        *reinterpret_cast<__nv_bfloat162*>(&sWlo[k * LDS_A + n0 + 2]) =
            __nv_bfloat162(__float2bfloat16(v.z - __bfloat162float(hz)),
                           __float2bfloat16(v.w - __bfloat162float(hw)));
    }

    // ---- Stage A (means): fp32 -> bf16 hi/lo ----
    #pragma unroll
    for (int i = 0; i < 8; i++) {
        const int idx = tid + i * K2_THREADS;     // 0..2047 float4
        const int r   = idx >> 5;
        const int c0  = (idx & 31) * 4;
        const float4 v = *reinterpret_cast<const float4*>(
            &inout[(long long)(row0 + r) * D_DIM + c0]);
        const __nv_bfloat16 hx = __float2bfloat16(v.x);
        const __nv_bfloat16 hy = __float2bfloat16(v.y);
        const __nv_bfloat16 hz = __float2bfloat16(v.z);
        const __nv_bfloat16 hw = __float2bfloat16(v.w);
        *reinterpret_cast<__nv_bfloat162*>(&sAhi[r * LDS_A + c0]) =
            __nv_bfloat162(hx, hy);
        *reinterpret_cast<__nv_bfloat162*>(&sAhi[r * LDS_A + c0 + 2]) =
            __nv_bfloat162(hz, hw);
        *reinterpret_cast<__nv_bfloat162*>(&sAlo[r * LDS_A + c0]) =
            __nv_bfloat162(__float2bfloat16(v.x - __bfloat162float(hx)),
                           __float2bfloat16(v.y - __bfloat162float(hy)));
        *reinterpret_cast<__nv_bfloat162*>(&sAlo[r * LDS_A + c0 + 2]) =
            __nv_bfloat162(__float2bfloat16(v.z - __bfloat162float(hz)),
                           __float2bfloat16(v.w - __bfloat162float(hw)));
    }
    __syncthreads();

    // ---- WMMA GEMM, ks-pipelined: load ks+1 before computing ks ----
    const int wr = (wid >> 2) * 32;   // 0 or 32
    const int wc = (wid & 3) * 32;    // 0,32,64,96

    wmma::fragment<wmma::accumulator, 16, 16, 16, float> acc[2][2];
    #pragma unroll
    for (int i = 0; i < 2; i++)
        #pragma unroll
        for (int j = 0; j < 2; j++)
            wmma::fill_fragment(acc[i][j], 0.0f);

    FragSet fs[2];
    load_frags(fs[0], sAhi, sWhi, wr, wc, 0);

    #pragma unroll
    for (int ks = 0; ks < D_DIM / 16; ks++) {
        const int cur = ks & 1;
        if (ks + 1 < D_DIM / 16)
            load_frags(fs[cur ^ 1], sAhi, sWhi, wr, wc, ks + 1);

        #pragma unroll
        for (int i = 0; i < 2; i++)
            #pragma unroll
            for (int j = 0; j < 2; j++) {
                wmma::mma_sync(acc[i][j], fs[cur].aHi[i], fs[cur].bHi[j],
                               acc[i][j]);
                wmma::mma_sync(acc[i][j], fs[cur].aHi[i], fs[cur].bLo[j],
                               acc[i][j]);
                wmma::mma_sync(acc[i][j], fs[cur].aLo[i], fs[cur].bHi[j],
                               acc[i][j]);
            }
    }

    // ---- Epilogue: relu + store ----
    #pragma unroll
    for (int i = 0; i < 2; i++)
        #pragma unroll
        for (int j = 0; j < 2; j++) {
            #pragma unroll
            for (int e = 0; e < acc[i][j].num_elements; e++)
                acc[i][j].x[e] = fmaxf(acc[i][j].x[e], 0.0f);
            wmma::store_matrix_sync(
                &inout[(long long)(row0 + wr + i * 16) * D_DIM + wc + j * 16],
                acc[i][j], D_DIM, wmma::mem_row_major);
        }
}

extern "C" void kernel_launch(void* const* d_in, const int* in_sizes, int n_in,
                              void* d_out, int out_size)
{
    // Identify inputs by element count — robust to d_in ordering.
    int imax = 0, imin = 0;
    for (int i = 1; i < 3 && i < n_in; i++) {
        if (in_sizes[i] > in_sizes[imax]) imax = i;
        if (in_sizes[i] < in_sizes[imin]) imin = i;
    }
    const int imid = 3 - imax - imin;

    const float* features = (const float*)d_in[imax];
    const float* W        = (const float*)d_in[imin];
    const int*   sample   = (const int*)d_in[imid];

    float* out = (float*)d_out;

    const int n_rows = in_sizes[imid] / S_SAMPLES;   // 32768
    const int grid2  = n_rows / K2_ROWS;             // 512

    const int smem_bytes = (2 * SA_ELEMS + 2 * SW_ELEMS) * sizeof(__nv_bfloat16);

    cudaFuncSetAttribute(gemm_relu_kernel,
                         cudaFuncAttributeMaxDynamicSharedMemorySize,
                         smem_bytes);

    gather_mean_kernel<<<K1_GRID, K1_THREADS>>>(features, sample, out);
    gemm_relu_kernel<<<grid2, K2_THREADS, smem_bytes>>>(W, out);
}

// round 15
// speedup vs baseline: 1.3449x; 1.1127x over previous
#include <cuda_runtime.h>
#include <cuda_bf16.h>
#include <mma.h>
#include <cstdint>

using namespace nvcuda;

// GCNAggregator fused warp-specialized pipeline (single kernel):
//   producer warps 0-7 : gather + mean + bf16 hi/lo split -> smem A (2 bufs)
//   consumer warps 8-15: 3-term bf16-split WMMA + relu -> out
// Sync: named barriers full[buf]=1+buf, empty[buf]=3+buf (count 512).

#define D_DIM 128
#define S_SAMPLES 25
#define N_NODES 100000
#define N_ROWS 32768
#define TILE_ROWS 64
#define N_TILES (N_ROWS / TILE_ROWS)   // 512
#define THREADS 512
#define GRID 148

#define LDS_A 136                      // bf16 stride (272B rows)
#define SA_ELEMS (TILE_ROWS * LDS_A)   // 8704
#define SW_ELEMS (D_DIM * LDS_A)       // 17408
// smem: W hi/lo (2*17408) + A 2 bufs * hi/lo (2*2*8704) = 69632 bf16 = 139264 B
#define SMEM_BYTES ((2 * SW_ELEMS + 4 * SA_ELEMS) * 2)

#define BAR_SYNC(id)   asm volatile("bar.sync %0, %1;"   :: "r"(id), "n"(THREADS) : "memory")
#define BAR_ARRIVE(id) asm volatile("bar.arrive %0, %1;" :: "r"(id), "n"(THREADS) : "memory")

__global__ __launch_bounds__(THREADS, 1)
void gcn_fused_kernel(const float* __restrict__ features,
                      const int* __restrict__ sample,
                      const float* __restrict__ W,
                      float* __restrict__ out)
{
    extern __shared__ __nv_bfloat16 smem[];
    __nv_bfloat16* sWhi = smem;                     // [128][136]
    __nv_bfloat16* sWlo = smem + SW_ELEMS;
    __nv_bfloat16* sA   = smem + 2 * SW_ELEMS;      // [2][hi/lo][64][136]

    const int tid  = threadIdx.x;
    const int wid  = tid >> 5;       // 0..15
    const int lane = tid & 31;

    // ---- Stage W once (all 512 threads): fp32 -> bf16 hi/lo ----
    #pragma unroll
    for (int i = 0; i < 8; i++) {
        const int idx = tid + i * THREADS;        // 0..4095 float4
        const int k   = idx >> 5;                 // 0..127
        const int n0  = (idx & 31) * 4;
        const float4 v = *reinterpret_cast<const float4*>(&W[k * D_DIM + n0]);
        const __nv_bfloat16 hx = __float2bfloat16(v.x);
        const __nv_bfloat16 hy = __float2bfloat16(v.y);
        const __nv_bfloat16 hz = __float2bfloat16(v.z);
        const __nv_bfloat16 hw = __float2bfloat16(v.w);
        *reinterpret_cast<__nv_bfloat162*>(&sWhi[k * LDS_A + n0]) =
            __nv_bfloat162(hx, hy);
        *reinterpret_cast<__nv_bfloat162*>(&sWhi[k * LDS_A + n0 + 2]) =
            __nv_bfloat162(hz, hw);
        *reinterpret_cast<__nv_bfloat162*>(&sWlo[k * LDS_A + n0]) =
            __nv_bfloat162(__float2bfloat16(v.x - __bfloat162float(hx)),
                           __float2bfloat16(v.y - __bfloat162float(hy)));
        *reinterpret_cast<__nv_bfloat162*>(&sWlo[k * LDS_A + n0 + 2]) =
            __nv_bfloat162(__float2bfloat16(v.z - __bfloat162float(hz)),
                           __float2bfloat16(v.w - __bfloat162float(hw)));
    }
    __syncthreads();

    if (wid < 8) {
        // ================= PRODUCER: gather + mean + split =================
        const int k0 = lane * 4;
        for (int t = blockIdx.x, it = 0; t < N_TILES; t += GRID, ++it) {
            const int buf = it & 1;
            __nv_bfloat16* aHi = sA + buf * 2 * SA_ELEMS;
            __nv_bfloat16* aLo = aHi + SA_ELEMS;

            if (it >= 2) BAR_SYNC(3 + buf);     // wait buffer empty

            const int rowBase = t * TILE_ROWS + wid * 8;
            #pragma unroll
            for (int rr = 0; rr < 8; rr++) {
                const int row = rowBase + rr;
                const int* idxp = sample + (long long)row * S_SAMPLES;

                float4 acc = make_float4(0.f, 0.f, 0.f, 0.f);
                #pragma unroll
                for (int s = 0; s < S_SAMPLES; s++) {
                    int node = __ldg(&idxp[s]);                 // broadcast
                    node = min(max(node, 0), N_NODES - 1);      // clamp
                    const float4 v = *reinterpret_cast<const float4*>(
                        &features[(long long)node * D_DIM + k0]);
                    acc.x += v.x; acc.y += v.y; acc.z += v.z; acc.w += v.w;
                }
                const float inv = 1.0f / (float)S_SAMPLES;
                acc.x *= inv; acc.y *= inv; acc.z *= inv; acc.w *= inv;

                const __nv_bfloat16 hx = __float2bfloat16(acc.x);
                const __nv_bfloat16 hy = __float2bfloat16(acc.y);
                const __nv_bfloat16 hz = __float2bfloat16(acc.z);
                const __nv_bfloat16 hw = __float2bfloat16(acc.w);
                const int soff = (wid * 8 + rr) * LDS_A + k0;
                *reinterpret_cast<__nv_bfloat162*>(&aHi[soff]) =
                    __nv_bfloat162(hx, hy);
                *reinterpret_cast<__nv_bfloat162*>(&aHi[soff + 2]) =
                    __nv_bfloat162(hz, hw);
                *reinterpret_cast<__nv_bfloat162*>(&aLo[soff]) =
                    __nv_bfloat162(
                        __float2bfloat16(acc.x - __bfloat162float(hx)),
                        __float2bfloat16(acc.y - __bfloat162float(hy)));
                *reinterpret_cast<__nv_bfloat162*>(&aLo[soff + 2]) =
                    __nv_bfloat162(
                        __float2bfloat16(acc.z - __bfloat162float(hz)),
                        __float2bfloat16(acc.w - __bfloat162float(hw)));
            }
            __threadfence_block();              // STS visible before arrive
            BAR_ARRIVE(1 + buf);                // signal buffer full
        }
    } else {
        // ================= CONSUMER: WMMA + relu =================
        const int cw = wid - 8;                 // 0..7
        const int wr = (cw >> 2) * 32;          // 0 or 32
        const int wc = (cw & 3) * 32;           // 0,32,64,96

        for (int t = blockIdx.x, it = 0; t < N_TILES; t += GRID, ++it) {
            const int buf = it & 1;
            const __nv_bfloat16* aHi = sA + buf * 2 * SA_ELEMS;

            BAR_SYNC(1 + buf);                  // wait buffer full

            wmma::fragment<wmma::accumulator, 16, 16, 16, float> acc[2][2];
            #pragma unroll
            for (int i = 0; i < 2; i++)
                #pragma unroll
                for (int j = 0; j < 2; j++)
                    wmma::fill_fragment(acc[i][j], 0.0f);

            #pragma unroll
            for (int ks = 0; ks < D_DIM / 16; ks++) {
                wmma::fragment<wmma::matrix_a, 16, 16, 16, __nv_bfloat16,
                               wmma::row_major> fAhi[2], fAlo[2];
                wmma::fragment<wmma::matrix_b, 16, 16, 16, __nv_bfloat16,
                               wmma::row_major> fBhi[2], fBlo[2];

                #pragma unroll
                for (int i = 0; i < 2; i++) {
                    const __nv_bfloat16* pa =
                        &aHi[(wr + i * 16) * LDS_A + ks * 16];
                    wmma::load_matrix_sync(fAhi[i], pa, LDS_A);
                    wmma::load_matrix_sync(fAlo[i], pa + SA_ELEMS, LDS_A);
                }
                #pragma unroll
                for (int j = 0; j < 2; j++) {
                    const __nv_bfloat16* pb =
                        &sWhi[(ks * 16) * LDS_A + wc + j * 16];
                    wmma::load_matrix_sync(fBhi[j], pb, LDS_A);
                    wmma::load_matrix_sync(fBlo[j], pb + SW_ELEMS, LDS_A);
                }

                #pragma unroll
                for (int i = 0; i < 2; i++)
                    #pragma unroll
                    for (int j = 0; j < 2; j++) {
                        wmma::mma_sync(acc[i][j], fAhi[i], fBhi[j], acc[i][j]);
                        wmma::mma_sync(acc[i][j], fAhi[i], fBlo[j], acc[i][j]);
                        wmma::mma_sync(acc[i][j], fAlo[i], fBhi[j], acc[i][j]);
                    }
            }

            const long long row0 = (long long)t * TILE_ROWS;
            #pragma unroll
            for (int i = 0; i < 2; i++)
                #pragma unroll
                for (int j = 0; j < 2; j++) {
                    #pragma unroll
                    for (int e = 0; e < acc[i][j].num_elements; e++)
                        acc[i][j].x[e] = fmaxf(acc[i][j].x[e], 0.0f);
                    wmma::store_matrix_sync(
                        &out[(row0 + wr + i * 16) * D_DIM + wc + j * 16],
                        acc[i][j], D_DIM, wmma::mem_row_major);
                }

            BAR_ARRIVE(3 + buf);                // signal buffer empty
        }
    }
}

extern "C" void kernel_launch(void* const* d_in, const int* in_sizes, int n_in,
                              void* d_out, int out_size)
{
    // Identify inputs by element count — robust to d_in ordering.
    int imax = 0, imin = 0;
    for (int i = 1; i < 3 && i < n_in; i++) {
        if (in_sizes[i] > in_sizes[imax]) imax = i;
        if (in_sizes[i] < in_sizes[imin]) imin = i;
    }
    const int imid = 3 - imax - imin;

    const float* features = (const float*)d_in[imax];
    const float* W        = (const float*)d_in[imin];
    const int*   sample   = (const int*)d_in[imid];

    float* out = (float*)d_out;

    cudaFuncSetAttribute(gcn_fused_kernel,
                         cudaFuncAttributeMaxDynamicSharedMemorySize,
                         SMEM_BYTES);

    gcn_fused_kernel<<<GRID, THREADS, SMEM_BYTES>>>(features, sample, W, out);
}

// round 16
// speedup vs baseline: 1.4148x; 1.0519x over previous
#include <cuda_runtime.h>
#include <cuda_bf16.h>
#include <mma.h>
#include <cstdint>

using namespace nvcuda;

// GCNAggregator fused warp-specialized pipeline (single persistent kernel):
//   producer warps 0-7 : gather + mean + bf16 hi/lo split -> smem A (3 bufs)
//   consumer warps 8-15: 3-term bf16-split WMMA + relu -> out
// 1024 tiles of 32 rows -> near-perfect CTA balance (max 7 vs avg 6.92).

#define D_DIM 128
#define S_SAMPLES 25
#define N_NODES 100000
#define N_ROWS 32768
#define TILE_ROWS 32
#define N_TILES (N_ROWS / TILE_ROWS)   // 1024
#define THREADS 512
#define GRID 148
#define NBUF 3

#define LDS_A 136                      // bf16 stride (272B rows)
#define SA_ELEMS (TILE_ROWS * LDS_A)   // 4352
#define SW_ELEMS (D_DIM * LDS_A)       // 17408
// smem: W hi/lo + 3 A bufs (hi/lo) = (2*17408 + 3*2*4352) * 2B = 121,856 B
#define SMEM_BYTES ((2 * SW_ELEMS + NBUF * 2 * SA_ELEMS) * 2)

#define BAR_SYNC(id)   asm volatile("bar.sync %0, %1;"   :: "r"(id), "n"(THREADS) : "memory")
#define BAR_ARRIVE(id) asm volatile("bar.arrive %0, %1;" :: "r"(id), "n"(THREADS) : "memory")

__global__ __launch_bounds__(THREADS, 1)
void gcn_fused_kernel(const float* __restrict__ features,
                      const int* __restrict__ sample,
                      const float* __restrict__ W,
                      float* __restrict__ out)
{
    extern __shared__ __nv_bfloat16 smem[];
    __nv_bfloat16* sWhi = smem;                     // [128][136]
    __nv_bfloat16* sWlo = smem + SW_ELEMS;
    __nv_bfloat16* sA   = smem + 2 * SW_ELEMS;      // [NBUF][hi/lo][32][136]

    const int tid  = threadIdx.x;
    const int wid  = tid >> 5;       // 0..15
    const int lane = tid & 31;

    // ---- Stage W once (all 512 threads): fp32 -> bf16 hi/lo ----
    #pragma unroll
    for (int i = 0; i < 8; i++) {
        const int idx = tid + i * THREADS;        // 0..4095 float4
        const int k   = idx >> 5;                 // 0..127
        const int n0  = (idx & 31) * 4;
        const float4 v = *reinterpret_cast<const float4*>(&W[k * D_DIM + n0]);
        const __nv_bfloat16 hx = __float2bfloat16(v.x);
        const __nv_bfloat16 hy = __float2bfloat16(v.y);
        const __nv_bfloat16 hz = __float2bfloat16(v.z);
        const __nv_bfloat16 hw = __float2bfloat16(v.w);
        *reinterpret_cast<__nv_bfloat162*>(&sWhi[k * LDS_A + n0]) =
            __nv_bfloat162(hx, hy);
        *reinterpret_cast<__nv_bfloat162*>(&sWhi[k * LDS_A + n0 + 2]) =
            __nv_bfloat162(hz, hw);
        *reinterpret_cast<__nv_bfloat162*>(&sWlo[k * LDS_A + n0]) =
            __nv_bfloat162(__float2bfloat16(v.x - __bfloat162float(hx)),
                           __float2bfloat16(v.y - __bfloat162float(hy)));
        *reinterpret_cast<__nv_bfloat162*>(&sWlo[k * LDS_A + n0 + 2]) =
            __nv_bfloat162(__float2bfloat16(v.z - __bfloat162float(hz)),
                           __float2bfloat16(v.w - __bfloat162float(hw)));
    }
    __syncthreads();

    if (wid < 8) {
        // ================= PRODUCER: gather + mean + split =================
        const int k0 = lane * 4;
        int it = 0;
        for (int t = blockIdx.x; t < N_TILES; t += GRID, ++it) {
            const int buf = it % NBUF;
            __nv_bfloat16* aHi = sA + buf * 2 * SA_ELEMS;
            __nv_bfloat16* aLo = aHi + SA_ELEMS;

            if (it >= NBUF) BAR_SYNC(NBUF + 1 + buf);   // wait buffer empty

            const int rowBase = t * TILE_ROWS + wid * 4;  // ≡ 0 (mod 4)
            #pragma unroll
            for (int r = 0; r < 4; r++) {
                const int row = rowBase + r;
                // row ≡ r (mod 4) => row*25 - r ≡ 0 (mod 4): int4-aligned.
                const int4* ip = reinterpret_cast<const int4*>(
                    sample + (long long)row * S_SAMPLES - r);
                int va[28];
                #pragma unroll
                for (int i = 0; i < 7; i++) {
                    const int4 q = __ldg(&ip[i]);
                    va[4 * i]     = q.x; va[4 * i + 1] = q.y;
                    va[4 * i + 2] = q.z; va[4 * i + 3] = q.w;
                }

                float4 acc = make_float4(0.f, 0.f, 0.f, 0.f);
                #pragma unroll
                for (int s = 0; s < S_SAMPLES; s++) {
                    int node = va[s + r];            // const idx (unrolled)
                    node = min(max(node, 0), N_NODES - 1);
                    const float4 v = *reinterpret_cast<const float4*>(
                        &features[(long long)node * D_DIM + k0]);
                    acc.x += v.x; acc.y += v.y; acc.z += v.z; acc.w += v.w;
                }
                const float inv = 1.0f / (float)S_SAMPLES;
                acc.x *= inv; acc.y *= inv; acc.z *= inv; acc.w *= inv;

                const __nv_bfloat16 hx = __float2bfloat16(acc.x);
                const __nv_bfloat16 hy = __float2bfloat16(acc.y);
                const __nv_bfloat16 hz = __float2bfloat16(acc.z);
                const __nv_bfloat16 hw = __float2bfloat16(acc.w);
                const int soff = (wid * 4 + r) * LDS_A + k0;
                *reinterpret_cast<__nv_bfloat162*>(&aHi[soff]) =
                    __nv_bfloat162(hx, hy);
                *reinterpret_cast<__nv_bfloat162*>(&aHi[soff + 2]) =
                    __nv_bfloat162(hz, hw);
                *reinterpret_cast<__nv_bfloat162*>(&aLo[soff]) =
                    __nv_bfloat162(
                        __float2bfloat16(acc.x - __bfloat162float(hx)),
                        __float2bfloat16(acc.y - __bfloat162float(hy)));
                *reinterpret_cast<__nv_bfloat162*>(&aLo[soff + 2]) =
                    __nv_bfloat162(
                        __float2bfloat16(acc.z - __bfloat162float(hz)),
                        __float2bfloat16(acc.w - __bfloat162float(hw)));
            }
            __threadfence_block();
            BAR_ARRIVE(1 + buf);                    // signal buffer full
        }
    } else {
        // ================= CONSUMER: WMMA + relu =================
        const int cw = wid - 8;                 // 0..7
        const int wr = (cw >> 2) * 16;          // 0 or 16
        const int wc = (cw & 3) * 32;           // 0,32,64,96

        int it = 0;
        for (int t = blockIdx.x; t < N_TILES; t += GRID, ++it) {
            const int buf = it % NBUF;
            const __nv_bfloat16* aHi = sA + buf * 2 * SA_ELEMS;

            BAR_SYNC(1 + buf);                  // wait buffer full

            wmma::fragment<wmma::accumulator, 16, 16, 16, float> acc[2];
            wmma::fill_fragment(acc[0], 0.0f);
            wmma::fill_fragment(acc[1], 0.0f);

            #pragma unroll
            for (int ks = 0; ks < D_DIM / 16; ks++) {
                wmma::fragment<wmma::matrix_a, 16, 16, 16, __nv_bfloat16,
                               wmma::row_major> fAhi, fAlo;
                wmma::fragment<wmma::matrix_b, 16, 16, 16, __nv_bfloat16,
                               wmma::row_major> fBhi[2], fBlo[2];

                const __nv_bfloat16* pa = &aHi[wr * LDS_A + ks * 16];
                wmma::load_matrix_sync(fAhi, pa, LDS_A);
                wmma::load_matrix_sync(fAlo, pa + SA_ELEMS, LDS_A);

                #pragma unroll
                for (int j = 0; j < 2; j++) {
                    const __nv_bfloat16* pb =
                        &sWhi[(ks * 16) * LDS_A + wc + j * 16];
                    wmma::load_matrix_sync(fBhi[j], pb, LDS_A);
                    wmma::load_matrix_sync(fBlo[j], pb + SW_ELEMS, LDS_A);
                }

                #pragma unroll
                for (int j = 0; j < 2; j++) {
                    wmma::mma_sync(acc[j], fAhi, fBhi[j], acc[j]);
                    wmma::mma_sync(acc[j], fAhi, fBlo[j], acc[j]);
                    wmma::mma_sync(acc[j], fAlo, fBhi[j], acc[j]);
                }
            }

            const long long row0 = (long long)t * TILE_ROWS;
            #pragma unroll
            for (int j = 0; j < 2; j++) {
                #pragma unroll
                for (int e = 0; e < acc[j].num_elements; e++)
                    acc[j].x[e] = fmaxf(acc[j].x[e], 0.0f);
                wmma::store_matrix_sync(
                    &out[(row0 + wr) * D_DIM + wc + j * 16],
                    acc[j], D_DIM, wmma::mem_row_major);
            }

            BAR_ARRIVE(NBUF + 1 + buf);         // signal buffer empty
        }
    }
}

extern "C" void kernel_launch(void* const* d_in, const int* in_sizes, int n_in,
                              void* d_out, int out_size)
{
    // Identify inputs by element count — robust to d_in ordering.
    int imax = 0, imin = 0;
    for (int i = 1; i < 3 && i < n_in; i++) {
        if (in_sizes[i] > in_sizes[imax]) imax = i;
        if (in_sizes[i] < in_sizes[imin]) imin = i;
    }
    const int imid = 3 - imax - imin;

    const float* features = (const float*)d_in[imax];
    const float* W        = (const float*)d_in[imin];
    const int*   sample   = (const int*)d_in[imid];

    float* out = (float*)d_out;

    cudaFuncSetAttribute(gcn_fused_kernel,
                         cudaFuncAttributeMaxDynamicSharedMemorySize,
                         SMEM_BYTES);

    gcn_fused_kernel<<<GRID, THREADS, SMEM_BYTES>>>(features, sample, W, out);
}